// round 1
// baseline (speedup 1.0000x reference)
#include <cuda_runtime.h>
#include <cuda_bf16.h>
#include <cstdint>

// Problem constants
#define B_  2
#define T_  2048
#define D_  1024
#define H_  16
#define DH_ 64
#define TOPK_ 32
#define BH_ (B_*H_)

// ---------------------------------------------------------------------------
// Scratch (static device globals; no allocation allowed)
// ---------------------------------------------------------------------------
__device__ __align__(16) float g_Q[(size_t)BH_ * T_ * DH_];   // [BH,T,DH]
__device__ __align__(16) float g_K[(size_t)BH_ * T_ * DH_];
__device__ __align__(16) float g_V[(size_t)BH_ * T_ * DH_];
__device__ __align__(16) float g_S[(size_t)BH_ * T_ * T_];    // [BH,T,T] scores, 536MB
__device__ __align__(16) float g_AO[(size_t)B_ * T_ * D_];    // attn out [B,T,D]

// ---------------------------------------------------------------------------
// Generic C = A @ B^T GEMM, 128x128x16 tile, 256 threads, 8x8 micro-tile.
// A: [M,K] row-major, Bm: [N,K] row-major. M%128==0, N%128==0, K%16==0.
// EPI: 0 plain, 1 +bias, 2 head-split (QKV), 3 scale 0.125 (scores)
// ---------------------------------------------------------------------------
#define EPI_PLAIN 0
#define EPI_BIAS  1
#define EPI_HEADS 2
#define EPI_SCALE 3

template<int EPI>
__global__ __launch_bounds__(256)
void gemm_abt(const float* __restrict__ A, const float* __restrict__ Bm,
              const float* __restrict__ bias, float* __restrict__ C,
              int M, int N, int K,
              long strideA, long strideB, long strideC)
{
    const float* Ab = A + (long)blockIdx.z * strideA;
    const float* Bb = Bm + (long)blockIdx.z * strideB;
    float* Cb = C + (long)blockIdx.z * strideC;

    __shared__ float AsT[16][128];
    __shared__ float BsT[16][128];

    const int tid = threadIdx.x;
    const int tx = tid & 15;      // column group
    const int ty = tid >> 4;      // row group
    const int m0 = blockIdx.y * 128;
    const int n0 = blockIdx.x * 128;

    float acc[8][8];
#pragma unroll
    for (int i = 0; i < 8; i++)
#pragma unroll
        for (int j = 0; j < 8; j++) acc[i][j] = 0.f;

    for (int k0 = 0; k0 < K; k0 += 16) {
#pragma unroll
        for (int i = 0; i < 2; i++) {
            int idx  = tid * 2 + i;      // 0..511
            int row  = idx >> 2;         // 0..127
            int col4 = (idx & 3) * 4;    // 0,4,8,12
            float4 va = *(const float4*)(Ab + (long)(m0 + row) * K + k0 + col4);
            AsT[col4 + 0][row] = va.x;
            AsT[col4 + 1][row] = va.y;
            AsT[col4 + 2][row] = va.z;
            AsT[col4 + 3][row] = va.w;
            float4 vb = *(const float4*)(Bb + (long)(n0 + row) * K + k0 + col4);
            BsT[col4 + 0][row] = vb.x;
            BsT[col4 + 1][row] = vb.y;
            BsT[col4 + 2][row] = vb.z;
            BsT[col4 + 3][row] = vb.w;
        }
        __syncthreads();
#pragma unroll
        for (int k = 0; k < 16; k++) {
            float a[8], b[8];
            *(float4*)&a[0] = *(const float4*)&AsT[k][ty * 8];
            *(float4*)&a[4] = *(const float4*)&AsT[k][ty * 8 + 4];
            *(float4*)&b[0] = *(const float4*)&BsT[k][tx * 8];
            *(float4*)&b[4] = *(const float4*)&BsT[k][tx * 8 + 4];
#pragma unroll
            for (int i = 0; i < 8; i++)
#pragma unroll
                for (int j = 0; j < 8; j++)
                    acc[i][j] += a[i] * b[j];
        }
        __syncthreads();
    }

#pragma unroll
    for (int i = 0; i < 8; i++) {
        int m = m0 + ty * 8 + i;
#pragma unroll
        for (int j = 0; j < 8; j += 4) {
            int n = n0 + tx * 8 + j;
            float4 r = make_float4(acc[i][j], acc[i][j + 1], acc[i][j + 2], acc[i][j + 3]);
            if (EPI == EPI_PLAIN) {
                *(float4*)(Cb + (long)m * N + n) = r;
            } else if (EPI == EPI_BIAS) {
                r.x += bias[n]; r.y += bias[n + 1]; r.z += bias[n + 2]; r.w += bias[n + 3];
                *(float4*)(Cb + (long)m * N + n) = r;
            } else if (EPI == EPI_SCALE) {
                r.x *= 0.125f; r.y *= 0.125f; r.z *= 0.125f; r.w *= 0.125f;
                *(float4*)(Cb + (long)m * N + n) = r;
            } else { // EPI_HEADS: N==1024, write [BH,T,DH]
                int bb = m >> 11, t = m & (T_ - 1);
                int h = n >> 6, inner = n & (DH_ - 1);
                float* dst = Cb + (((long)(bb * H_ + h) * T_ + t) * DH_ + inner);
                *(float4*)dst = r;
            }
        }
    }
}

// ---------------------------------------------------------------------------
// Top-k threshold (exact, via radix bisection on order-preserving uint),
// softmax over survivors, sparse P@V. One block (128 thr) per query row.
// ---------------------------------------------------------------------------
__device__ __forceinline__ unsigned uencode(float f) {
    unsigned b = __float_as_uint(f);
    return (b & 0x80000000u) ? ~b : (b | 0x80000000u);
}
__device__ __forceinline__ float udecode(unsigned u) {
    unsigned b = (u & 0x80000000u) ? (u & 0x7fffffffu) : ~u;
    return __uint_as_float(b);
}

__global__ __launch_bounds__(128)
void topk_softmax_av(const float* __restrict__ S, const float* __restrict__ V,
                     float* __restrict__ O)
{
    __shared__ int      s_list[T_];
    __shared__ float    s_p[T_];
    __shared__ unsigned s_red[4];
    __shared__ float    s_fred[4];
    __shared__ int      s_cnt;
    __shared__ float    s_inv;

    const long row = blockIdx.x;            // bh*T + tq
    const int bh = (int)(row >> 11);
    const int tq = (int)(row & (T_ - 1));
    const float* Srow = S + row * T_;
    const int tid = threadIdx.x, lane = tid & 31, warp = tid >> 5;

    // Load 16 scores/thread (coalesced), encode to ordered uints in registers
    unsigned uloc[16];
#pragma unroll
    for (int i = 0; i < 16; i++)
        uloc[i] = uencode(Srow[tid + i * 128]);

    // Row max (in uint domain == float domain under monotone encoding)
    unsigned mx = 0;
#pragma unroll
    for (int i = 0; i < 16; i++) mx = max(mx, uloc[i]);
#pragma unroll
    for (int off = 16; off; off >>= 1)
        mx = max(mx, __shfl_xor_sync(0xffffffffu, mx, off));
    if (lane == 0) s_red[warp] = mx;
    __syncthreads();
    unsigned umax = max(max(s_red[0], s_red[1]), max(s_red[2], s_red[3]));
    __syncthreads();

    // Radix bisection: largest v with count(u >= v) >= TOPK  == kth largest
    unsigned prefix = 0;
    for (int bit = 31; bit >= 0; --bit) {
        unsigned cand = prefix | (1u << bit);
        if (cand > umax) continue;                 // uniform across block
        int c = 0;
#pragma unroll
        for (int i = 0; i < 16; i++) c += (uloc[i] >= cand);
#pragma unroll
        for (int off = 16; off; off >>= 1)
            c += __shfl_xor_sync(0xffffffffu, c, off);
        if (lane == 0) s_red[warp] = (unsigned)c;
        __syncthreads();
        int tot = (int)(s_red[0] + s_red[1] + s_red[2] + s_red[3]);
        __syncthreads();
        if (tot >= TOPK_) prefix = cand;
    }
    const unsigned uthr = prefix;
    const float m = udecode(umax);

    // Compact survivors, accumulate softmax denominator
    if (tid == 0) s_cnt = 0;
    __syncthreads();
    float lsum = 0.f;
#pragma unroll
    for (int i = 0; i < 16; i++) {
        if (uloc[i] >= uthr) {
            float p = __expf(udecode(uloc[i]) - m);
            lsum += p;
            int pos = atomicAdd(&s_cnt, 1);
            s_list[pos] = tid + i * 128;
            s_p[pos] = p;
        }
    }
#pragma unroll
    for (int off = 16; off; off >>= 1)
        lsum += __shfl_xor_sync(0xffffffffu, lsum, off);
    if (lane == 0) s_fred[warp] = lsum;
    __syncthreads();
    if (tid == 0) s_inv = 1.f / (s_fred[0] + s_fred[1] + s_fred[2] + s_fred[3]);
    __syncthreads();

    // Sparse attn @ V : 64 threads, one output dim each
    if (tid < DH_) {
        const int cnt = s_cnt;
        const float inv = s_inv;
        const float* Vb = V + (long)bh * T_ * DH_;
        float acc = 0.f;
        for (int e = 0; e < cnt; e++)
            acc += s_p[e] * Vb[(long)s_list[e] * DH_ + tid];
        const int bb = bh >> 4, h = bh & (H_ - 1);
        O[((long)(bb * T_ + tq)) * D_ + h * DH_ + tid] = acc * inv;
    }
}

// ---------------------------------------------------------------------------
// Launch
// ---------------------------------------------------------------------------
extern "C" void kernel_launch(void* const* d_in, const int* in_sizes, int n_in,
                              void* d_out, int out_size)
{
    const float* x    = (const float*)d_in[0];
    const float* Wq   = (const float*)d_in[1];
    const float* Wk   = (const float*)d_in[2];
    const float* Wv   = (const float*)d_in[3];
    const float* Wo_w = (const float*)d_in[4];
    const float* Wo_b = (const float*)d_in[5];
    float* out = (float*)d_out;

    float *pQ, *pK, *pV, *pS, *pAO;
    cudaGetSymbolAddress((void**)&pQ,  g_Q);
    cudaGetSymbolAddress((void**)&pK,  g_K);
    cudaGetSymbolAddress((void**)&pV,  g_V);
    cudaGetSymbolAddress((void**)&pS,  g_S);
    cudaGetSymbolAddress((void**)&pAO, g_AO);

    const int M = B_ * T_;   // 4096

    // 1) QKV projections (head-split epilogue)
    {
        dim3 grid(D_ / 128, M / 128, 1);
        gemm_abt<EPI_HEADS><<<grid, 256>>>(x, Wq, nullptr, pQ, M, D_, D_, 0, 0, 0);
        gemm_abt<EPI_HEADS><<<grid, 256>>>(x, Wk, nullptr, pK, M, D_, D_, 0, 0, 0);
        gemm_abt<EPI_HEADS><<<grid, 256>>>(x, Wv, nullptr, pV, M, D_, D_, 0, 0, 0);
    }

    // 2) Scores: S[bh] = Q[bh] @ K[bh]^T * 0.125   (batched over 32 bh)
    {
        dim3 grid(T_ / 128, T_ / 128, BH_);
        gemm_abt<EPI_SCALE><<<grid, 256>>>(pQ, pK, nullptr, pS, T_, T_, DH_,
                                           (long)T_ * DH_, (long)T_ * DH_,
                                           (long)T_ * T_);
    }

    // 3) Top-k threshold + softmax + sparse AV  -> g_AO [B,T,D]
    {
        dim3 grid(BH_ * T_, 1, 1);   // 65536 blocks
        topk_softmax_av<<<grid, 128>>>(pS, pV, pAO);
    }

    // 4) Output projection with bias -> d_out
    {
        dim3 grid(D_ / 128, M / 128, 1);
        gemm_abt<EPI_BIAS><<<grid, 256>>>(pAO, Wo_w, Wo_b, out, M, D_, D_, 0, 0, 0);
    }
}